// round 3
// baseline (speedup 1.0000x reference)
#include <cuda_runtime.h>
#include <cuda_bf16.h>
#include <math.h>

#define NN 50000
#define NE 800000
#define NG 256
#define H 64
#define BN_EPS 1e-5f

// ------------------------ device scratch (no allocs allowed) -----------------
__device__ int   g_flag;
__device__ int   g_src[NE];
__device__ int   g_dst[NE];
__device__ int   g_batch[NN];
__device__ int   g_cnt[NN];          // statically zero; re-zeroed by scan each run
__device__ int   g_rowstart[NN + 1];
__device__ int   g_cursor[NN];
__device__ float g_invcnt[NN];
__device__ int   g_csr_src[NE];
__device__ float g_y[NN * H];        // Y = A @ Wl
__device__ float g_z[NN * H];        // Z = A @ Wr + bias
__device__ float g_hA[NN * H];
__device__ float g_hB[NN * H];
__device__ float g_pacc[NG * H];     // statically zero; re-zeroed by poolnorm
__device__ float g_pcnt[NG];         // statically zero; re-zeroed by final_kernel
__device__ float g_pool[NG * H];
__device__ float g_t1[NG * 256];
__device__ float g_t2[NG * 128];
__device__ float g_t3[NG * 64];

// ------------------------ dtype probe ---------------------------------------
__global__ void detect_kernel(const long long* ei, const long long* bt) {
    __shared__ int bad;
    if (threadIdx.x == 0) bad = 0;
    __syncthreads();
    long long v = ei[threadIdx.x];
    if (v < 0 || v >= NN) bad = 1;
    long long b = bt[threadIdx.x];
    if (b < 0 || b >= NG) bad = 1;
    __syncthreads();
    if (threadIdx.x == 0) g_flag = bad ? 0 : 1;
}

// convert + histogram fused (g_cnt must be zero on entry; scan re-zeroes it)
__global__ void convert_kernel(const void* ei, const void* bt) {
    int i = blockIdx.x * blockDim.x + threadIdx.x;
    bool is64 = (g_flag != 0);
    if (i < NE) {
        int s, d;
        if (is64) {
            const long long* p = (const long long*)ei;
            s = (int)p[i]; d = (int)p[NE + i];
        } else {
            const int* p = (const int*)ei;
            s = p[i]; d = p[NE + i];
        }
        g_src[i] = s; g_dst[i] = d;
        atomicAdd(&g_cnt[d], 1);
    }
    if (i < NN) {
        if (is64) g_batch[i] = (int)((const long long*)bt)[i];
        else      g_batch[i] = ((const int*)bt)[i];
    }
}

// ------------------------ chunked shuffle scan (1 block, 1024 threads) ------
__global__ void scan_kernel() {
    const int C = (NN + 1023) / 1024;   // 49
    int tid = threadIdx.x;
    int base = tid * C;
    int s = 0;
#pragma unroll 7
    for (int j = 0; j < C; j++) {
        int idx = base + j;
        if (idx < NN) s += g_cnt[idx];
    }
    int lane = tid & 31, wid = tid >> 5;
    int v = s;
#pragma unroll
    for (int off = 1; off < 32; off <<= 1) {
        int t = __shfl_up_sync(0xffffffffu, v, off);
        if (lane >= off) v += t;
    }
    __shared__ int wsum[32];
    if (lane == 31) wsum[wid] = v;
    __syncthreads();
    if (wid == 0) {
        int w = wsum[lane];
#pragma unroll
        for (int off = 1; off < 32; off <<= 1) {
            int t = __shfl_up_sync(0xffffffffu, w, off);
            if (lane >= off) w += t;
        }
        wsum[lane] = w;
    }
    __syncthreads();
    int pref = v - s + (wid > 0 ? wsum[wid - 1] : 0);   // exclusive prefix
#pragma unroll 7
    for (int j = 0; j < C; j++) {
        int idx = base + j;
        if (idx < NN) {
            int c = g_cnt[idx];
            g_rowstart[idx] = pref;
            g_cursor[idx] = pref;
            g_invcnt[idx] = 1.0f / (float)max(c, 1);
            pref += c;
            g_cnt[idx] = 0;                     // reset for next replay
        }
    }
    if (tid == 0) g_rowstart[NN] = NE;
}

__global__ void fill_kernel() {
    int e = blockIdx.x * blockDim.x + threadIdx.x;
    if (e < NE) {
        int d = g_dst[e];
        int pos = atomicAdd(&g_cursor[d], 1);
        g_csr_src[pos] = g_src[e];
    }
}

// ------------------ fused dual GEMM: Y = A@Wl, Z = A@Wr + bias --------------
// A: [NN,K], Wl/Wr: [K,64]. 128-row x 128-col tile, 256 threads, 8x8 microtile.
template <int K>
__launch_bounds__(256)
__global__ void gemm_fused(const float* __restrict__ A,
                           const float* __restrict__ Wl,
                           const float* __restrict__ Wr,
                           const float* __restrict__ bias,
                           float* __restrict__ Y, float* __restrict__ Z) {
    __shared__ float As[128 * 33];
    __shared__ float Ws[32 * 128];
    int m0 = blockIdx.x * 128;
    int tid = threadIdx.x;
    int tr = tid >> 4, tc = tid & 15;

    float acc[8][8];
#pragma unroll
    for (int r = 0; r < 8; r++)
#pragma unroll
        for (int c = 0; c < 8; c++) acc[r][c] = 0.f;

    for (int k0 = 0; k0 < K; k0 += 32) {
#pragma unroll
        for (int i = 0; i < 16; i++) {
            int idx = i * 256 + tid;
            int r = idx >> 5, c = idx & 31;
            int gr = m0 + r;
            As[r * 33 + c] = (gr < NN) ? A[gr * K + k0 + c] : 0.f;
        }
#pragma unroll
        for (int i = 0; i < 16; i++) {
            int idx = i * 256 + tid;
            int r = idx >> 7, c = idx & 127;
            Ws[idx] = (c < 64) ? Wl[(k0 + r) * 64 + c] : Wr[(k0 + r) * 64 + (c - 64)];
        }
        __syncthreads();
#pragma unroll
        for (int k = 0; k < 32; k++) {
            float a[8], w[8];
#pragma unroll
            for (int r = 0; r < 8; r++) a[r] = As[(tr * 8 + r) * 33 + k];
            float4 w0 = *(const float4*)&Ws[k * 128 + tc * 8];
            float4 w1 = *(const float4*)&Ws[k * 128 + tc * 8 + 4];
            w[0] = w0.x; w[1] = w0.y; w[2] = w0.z; w[3] = w0.w;
            w[4] = w1.x; w[5] = w1.y; w[6] = w1.z; w[7] = w1.w;
#pragma unroll
            for (int r = 0; r < 8; r++)
#pragma unroll
                for (int c = 0; c < 8; c++) acc[r][c] = fmaf(a[r], w[c], acc[r][c]);
        }
        __syncthreads();
    }

    bool isZ = (tc >= 8);
    int col = (tc & 7) * 8;
    float bv[8];
#pragma unroll
    for (int c = 0; c < 8; c++) bv[c] = isZ ? bias[col + c] : 0.f;
    float* O = isZ ? Z : Y;
#pragma unroll
    for (int r = 0; r < 8; r++) {
        int gr = m0 + tr * 8 + r;
        if (gr < NN) {
            float4 v0, v1;
            v0.x = acc[r][0] + bv[0]; v0.y = acc[r][1] + bv[1];
            v0.z = acc[r][2] + bv[2]; v0.w = acc[r][3] + bv[3];
            v1.x = acc[r][4] + bv[4]; v1.y = acc[r][5] + bv[5];
            v1.z = acc[r][6] + bv[6]; v1.w = acc[r][7] + bv[7];
            *(float4*)&O[gr * 64 + col] = v0;
            *(float4*)&O[gr * 64 + col + 4] = v1;
        }
    }
}

// -------- aggregation + combine: h = ic * sum(Y[src]) + Z  (warp/node) ------
template <bool POOL>
__global__ void aggregate_kernel(float* __restrict__ Hout) {
    int w = (blockIdx.x * blockDim.x + threadIdx.x) >> 5;
    int lane = threadIdx.x & 31;
    if (w >= NN) return;
    int s0 = g_rowstart[w], s1 = g_rowstart[w + 1];
    float ax = 0.f, ay = 0.f;
    for (int k = s0; k < s1; k++) {
        int s = g_csr_src[k];
        float2 v = *(const float2*)&g_y[s * 64 + lane * 2];
        ax += v.x; ay += v.y;
    }
    float ic = g_invcnt[w];
    float2 z = *(const float2*)&g_z[w * 64 + lane * 2];
    float ox = ax * ic + z.x, oy = ay * ic + z.y;
    if (POOL) {
        int g = g_batch[w];
        atomicAdd(&g_pacc[g * 64 + lane * 2 + 0], ox);
        atomicAdd(&g_pacc[g * 64 + lane * 2 + 1], oy);
        if (lane == 0) atomicAdd(&g_pcnt[g], 1.f);
    } else {
        float2 o; o.x = ox; o.y = oy;
        *(float2*)&Hout[w * 64 + lane * 2] = o;
    }
}

// normalize pool; re-zero pacc for next replay (pcnt zeroed in final_kernel)
__global__ void poolnorm_kernel() {
    int i = blockIdx.x * blockDim.x + threadIdx.x;
    if (i < NG * H) {
        float c = g_pcnt[i >> 6];
        g_pool[i] = g_pacc[i] / fmaxf(c, 1.f);
        g_pacc[i] = 0.f;
    }
}

// ---------------- fused head layer: X = tanh(BN(A@W + b)) -------------------
// grid = N output features, block = 256 graph rows
template <int K, int N>
__global__ void head_kernel(const float* __restrict__ A, const float* __restrict__ W,
                            const float* __restrict__ b,
                            const float* __restrict__ gam, const float* __restrict__ bet,
                            float* __restrict__ X) {
    int j = blockIdx.x, i = threadIdx.x;
    float acc = b[j];
#pragma unroll 8
    for (int k = 0; k < K; k++) acc = fmaf(A[i * K + k], W[k * N + j], acc);
    __shared__ float red[256];
    red[i] = acc;
    __syncthreads();
    for (int off = 128; off > 0; off >>= 1) {
        if (i < off) red[i] += red[i + off];
        __syncthreads();
    }
    float mean = red[0] * (1.f / 256.f);
    __syncthreads();
    float d = acc - mean;
    red[i] = d * d;
    __syncthreads();
    for (int off = 128; off > 0; off >>= 1) {
        if (i < off) red[i] += red[i + off];
        __syncthreads();
    }
    float var = red[0] * (1.f / 256.f);
    X[i * N + j] = tanhf(d * rsqrtf(var + BN_EPS) * gam[j] + bet[j]);
}

// final linear (no BN); also re-zeroes g_pcnt for the next replay
__global__ void final_kernel(const float* __restrict__ A, const float* __restrict__ W,
                             const float* __restrict__ b, float* __restrict__ out) {
    int j = blockIdx.x, i = threadIdx.x;   // 10 blocks x 256 rows
    float acc = b[j];
#pragma unroll 8
    for (int k = 0; k < 64; k++) acc = fmaf(A[i * 64 + k], W[k * 10 + j], acc);
    out[i * 10 + j] = acc;
    if (j == 0) g_pcnt[i] = 0.f;
}

// ------------------------ launch --------------------------------------------
extern "C" void kernel_launch(void* const* d_in, const int* in_sizes, int n_in,
                              void* d_out, int out_size) {
    const float* x      = (const float*)d_in[0];
    const void*  ei     = d_in[1];
    const void*  bt     = d_in[2];
    const float* W1l    = (const float*)d_in[3];
    const float* b1l    = (const float*)d_in[4];
    const float* W1r    = (const float*)d_in[5];
    const float* W2l    = (const float*)d_in[6];
    const float* b2l    = (const float*)d_in[7];
    const float* W2r    = (const float*)d_in[8];
    const float* W3l    = (const float*)d_in[9];
    const float* b3l    = (const float*)d_in[10];
    const float* W3r    = (const float*)d_in[11];
    const float* lin1_w = (const float*)d_in[12];
    const float* lin1_b = (const float*)d_in[13];
    const float* g1     = (const float*)d_in[14];
    const float* be1    = (const float*)d_in[15];
    const float* lin2_w = (const float*)d_in[16];
    const float* lin2_b = (const float*)d_in[17];
    const float* g2     = (const float*)d_in[18];
    const float* be2    = (const float*)d_in[19];
    const float* lin3_w = (const float*)d_in[20];
    const float* lin3_b = (const float*)d_in[21];
    const float* g3     = (const float*)d_in[22];
    const float* be3    = (const float*)d_in[23];
    const float* lin4_w = (const float*)d_in[24];
    const float* lin4_b = (const float*)d_in[25];
    float* out = (float*)d_out;

    float *pY, *pZ, *pHA, *pHB, *pPool, *pT1, *pT2, *pT3;
    cudaGetSymbolAddress((void**)&pY,    g_y);
    cudaGetSymbolAddress((void**)&pZ,    g_z);
    cudaGetSymbolAddress((void**)&pHA,   g_hA);
    cudaGetSymbolAddress((void**)&pHB,   g_hB);
    cudaGetSymbolAddress((void**)&pPool, g_pool);
    cudaGetSymbolAddress((void**)&pT1,   g_t1);
    cudaGetSymbolAddress((void**)&pT2,   g_t2);
    cudaGetSymbolAddress((void**)&pT3,   g_t3);

    const int EB = (NE + 255) / 256;          // 3125
    const int MB = (NN + 127) / 128;          // 391
    const int WB = (NN * 32 + 255) / 256;     // 6250

    detect_kernel<<<1, 256>>>((const long long*)ei, (const long long*)bt);
    convert_kernel<<<EB, 256>>>(ei, bt);      // also builds degree histogram
    scan_kernel<<<1, 1024>>>();               // rowstart/cursor/invcnt + cnt reset
    fill_kernel<<<EB, 256>>>();

    // ---- layer 1 (K=128) ----
    gemm_fused<128><<<MB, 256>>>(x, W1l, W1r, b1l, pY, pZ);
    aggregate_kernel<false><<<WB, 256>>>(pHA);

    // ---- layer 2 (K=64) ----
    gemm_fused<64><<<MB, 256>>>(pHA, W2l, W2r, b2l, pY, pZ);
    aggregate_kernel<false><<<WB, 256>>>(pHB);

    // ---- layer 3 (K=64) + pooling fused ----
    gemm_fused<64><<<MB, 256>>>(pHB, W3l, W3r, b3l, pY, pZ);
    aggregate_kernel<true><<<WB, 256>>>(nullptr);

    poolnorm_kernel<<<(NG * H + 255) / 256, 256>>>();

    // ---- MLP head (fused gemm+BN+tanh per layer) ----
    head_kernel<64, 256><<<256, 256>>>(pPool, lin1_w, lin1_b, g1, be1, pT1);
    head_kernel<256, 128><<<128, 256>>>(pT1, lin2_w, lin2_b, g2, be2, pT2);
    head_kernel<128, 64><<<64, 256>>>(pT2, lin3_w, lin3_b, g3, be3, pT3);
    final_kernel<<<10, 256>>>(pT3, lin4_w, lin4_b, out);
}

// round 4
// speedup vs baseline: 1.0198x; 1.0198x over previous
#include <cuda_runtime.h>
#include <cuda_bf16.h>
#include <math.h>

#define NN 50000
#define NE 800000
#define NG 256
#define H 64
#define BN_EPS 1e-5f

// ------------------------ device scratch (no allocs allowed) -----------------
__device__ int   g_flag;
__device__ int   g_src[NE];
__device__ int   g_dst[NE];
__device__ int   g_batch[NN];
__device__ int   g_cnt[NN];          // statically zero; re-zeroed by scan each run
__device__ int   g_rowstart[NN + 1];
__device__ int   g_cursor[NN];
__device__ float g_invcnt[NN];
__device__ int   g_csr_src[NE];
__device__ float g_y[NN * H];        // Y = A @ Wl
__device__ float g_z[NN * H];        // Z = A @ Wr + bias
__device__ float g_hA[NN * H];
__device__ float g_hB[NN * H];
__device__ float g_pacc[NG * H];     // statically zero; re-zeroed by poolnorm
__device__ float g_pcnt[NG];         // statically zero; re-zeroed by final_kernel
__device__ float g_pool[NG * H];
__device__ float g_t1[NG * 256];
__device__ float g_t2[NG * 128];
__device__ float g_t3[NG * 64];

// ------------------------ dtype probe ---------------------------------------
__global__ void detect_kernel(const long long* ei, const long long* bt) {
    __shared__ int bad;
    if (threadIdx.x == 0) bad = 0;
    __syncthreads();
    long long v = ei[threadIdx.x];
    if (v < 0 || v >= NN) bad = 1;
    long long b = bt[threadIdx.x];
    if (b < 0 || b >= NG) bad = 1;
    __syncthreads();
    if (threadIdx.x == 0) g_flag = bad ? 0 : 1;
}

// convert + histogram fused (g_cnt must be zero on entry; scan re-zeroes it)
__global__ void convert_kernel(const void* ei, const void* bt) {
    int i = blockIdx.x * blockDim.x + threadIdx.x;
    bool is64 = (g_flag != 0);
    if (i < NE) {
        int s, d;
        if (is64) {
            const long long* p = (const long long*)ei;
            s = (int)p[i]; d = (int)p[NE + i];
        } else {
            const int* p = (const int*)ei;
            s = p[i]; d = p[NE + i];
        }
        g_src[i] = s; g_dst[i] = d;
        atomicAdd(&g_cnt[d], 1);
    }
    if (i < NN) {
        if (is64) g_batch[i] = (int)((const long long*)bt)[i];
        else      g_batch[i] = ((const int*)bt)[i];
    }
}

// ------------------------ chunked shuffle scan (1 block, 1024 threads) ------
__global__ void scan_kernel() {
    const int C = (NN + 1023) / 1024;   // 49
    int tid = threadIdx.x;
    int base = tid * C;
    int s = 0;
#pragma unroll 7
    for (int j = 0; j < C; j++) {
        int idx = base + j;
        if (idx < NN) s += g_cnt[idx];
    }
    int lane = tid & 31, wid = tid >> 5;
    int v = s;
#pragma unroll
    for (int off = 1; off < 32; off <<= 1) {
        int t = __shfl_up_sync(0xffffffffu, v, off);
        if (lane >= off) v += t;
    }
    __shared__ int wsum[32];
    if (lane == 31) wsum[wid] = v;
    __syncthreads();
    if (wid == 0) {
        int w = wsum[lane];
#pragma unroll
        for (int off = 1; off < 32; off <<= 1) {
            int t = __shfl_up_sync(0xffffffffu, w, off);
            if (lane >= off) w += t;
        }
        wsum[lane] = w;
    }
    __syncthreads();
    int pref = v - s + (wid > 0 ? wsum[wid - 1] : 0);   // exclusive prefix
#pragma unroll 7
    for (int j = 0; j < C; j++) {
        int idx = base + j;
        if (idx < NN) {
            int c = g_cnt[idx];
            g_rowstart[idx] = pref;
            g_cursor[idx] = pref;
            g_invcnt[idx] = 1.0f / (float)max(c, 1);
            pref += c;
            g_cnt[idx] = 0;                     // reset for next replay
        }
    }
    if (tid == 0) g_rowstart[NN] = NE;
}

__global__ void fill_kernel() {
    int e = blockIdx.x * blockDim.x + threadIdx.x;
    if (e < NE) {
        int d = g_dst[e];
        int pos = atomicAdd(&g_cursor[d], 1);
        g_csr_src[pos] = g_src[e];
    }
}

// ------------------ fused dual GEMM: Y = A@Wl, Z = A@Wr + bias --------------
// A: [NN,K], Wl/Wr: [K,64]. 128-row x 128-col tile, 256 threads, 8x8 microtile.
template <int K>
__launch_bounds__(256)
__global__ void gemm_fused(const float* __restrict__ A,
                           const float* __restrict__ Wl,
                           const float* __restrict__ Wr,
                           const float* __restrict__ bias,
                           float* __restrict__ Y, float* __restrict__ Z) {
    __shared__ float As[128 * 33];
    __shared__ float Ws[32 * 128];
    int m0 = blockIdx.x * 128;
    int tid = threadIdx.x;
    int tr = tid >> 4, tc = tid & 15;

    float acc[8][8];
#pragma unroll
    for (int r = 0; r < 8; r++)
#pragma unroll
        for (int c = 0; c < 8; c++) acc[r][c] = 0.f;

    for (int k0 = 0; k0 < K; k0 += 32) {
#pragma unroll
        for (int i = 0; i < 16; i++) {
            int idx = i * 256 + tid;
            int r = idx >> 5, c = idx & 31;
            int gr = m0 + r;
            As[r * 33 + c] = (gr < NN) ? A[gr * K + k0 + c] : 0.f;
        }
#pragma unroll
        for (int i = 0; i < 16; i++) {
            int idx = i * 256 + tid;
            int r = idx >> 7, c = idx & 127;
            Ws[idx] = (c < 64) ? Wl[(k0 + r) * 64 + c] : Wr[(k0 + r) * 64 + (c - 64)];
        }
        __syncthreads();
#pragma unroll
        for (int k = 0; k < 32; k++) {
            float a[8], w[8];
#pragma unroll
            for (int r = 0; r < 8; r++) a[r] = As[(tr * 8 + r) * 33 + k];
            float4 w0 = *(const float4*)&Ws[k * 128 + tc * 8];
            float4 w1 = *(const float4*)&Ws[k * 128 + tc * 8 + 4];
            w[0] = w0.x; w[1] = w0.y; w[2] = w0.z; w[3] = w0.w;
            w[4] = w1.x; w[5] = w1.y; w[6] = w1.z; w[7] = w1.w;
#pragma unroll
            for (int r = 0; r < 8; r++)
#pragma unroll
                for (int c = 0; c < 8; c++) acc[r][c] = fmaf(a[r], w[c], acc[r][c]);
        }
        __syncthreads();
    }

    bool isZ = (tc >= 8);
    int col = (tc & 7) * 8;
    float bv[8];
#pragma unroll
    for (int c = 0; c < 8; c++) bv[c] = isZ ? bias[col + c] : 0.f;
    float* O = isZ ? Z : Y;
#pragma unroll
    for (int r = 0; r < 8; r++) {
        int gr = m0 + tr * 8 + r;
        if (gr < NN) {
            float4 v0, v1;
            v0.x = acc[r][0] + bv[0]; v0.y = acc[r][1] + bv[1];
            v0.z = acc[r][2] + bv[2]; v0.w = acc[r][3] + bv[3];
            v1.x = acc[r][4] + bv[4]; v1.y = acc[r][5] + bv[5];
            v1.z = acc[r][6] + bv[6]; v1.w = acc[r][7] + bv[7];
            *(float4*)&O[gr * 64 + col] = v0;
            *(float4*)&O[gr * 64 + col + 4] = v1;
        }
    }
}

// -------- aggregation + combine: h = ic * sum(Y[src]) + Z  (warp/node) ------
template <bool POOL>
__global__ void aggregate_kernel(float* __restrict__ Hout) {
    int w = (blockIdx.x * blockDim.x + threadIdx.x) >> 5;
    int lane = threadIdx.x & 31;
    if (w >= NN) return;
    int s0 = g_rowstart[w], s1 = g_rowstart[w + 1];
    float ax = 0.f, ay = 0.f;
    for (int k = s0; k < s1; k++) {
        int s = g_csr_src[k];
        float2 v = *(const float2*)&g_y[s * 64 + lane * 2];
        ax += v.x; ay += v.y;
    }
    float ic = g_invcnt[w];
    float2 z = *(const float2*)&g_z[w * 64 + lane * 2];
    float ox = ax * ic + z.x, oy = ay * ic + z.y;
    if (POOL) {
        int g = g_batch[w];
        atomicAdd(&g_pacc[g * 64 + lane * 2 + 0], ox);
        atomicAdd(&g_pacc[g * 64 + lane * 2 + 1], oy);
        if (lane == 0) atomicAdd(&g_pcnt[g], 1.f);
    } else {
        float2 o; o.x = ox; o.y = oy;
        *(float2*)&Hout[w * 64 + lane * 2] = o;
    }
}

// normalize pool; re-zero pacc for next replay (pcnt zeroed in final_kernel)
__global__ void poolnorm_kernel() {
    int i = blockIdx.x * blockDim.x + threadIdx.x;
    if (i < NG * H) {
        float c = g_pcnt[i >> 6];
        g_pool[i] = g_pacc[i] / fmaxf(c, 1.f);
        g_pacc[i] = 0.f;
    }
}

// ---------------- fused head layer: X = tanh(BN(A@W + b)) -------------------
// grid = N output features (one column per block), block = 256 graph rows.
// A rows staged through shared memory with COALESCED tile loads; stride-33
// padding makes the per-row LDS reads conflict-free. W reads are uniform
// (same address across the block) -> single L1 transaction, broadcast.
template <int K, int N>
__launch_bounds__(256)
__global__ void head_kernel(const float* __restrict__ A, const float* __restrict__ W,
                            const float* __restrict__ b,
                            const float* __restrict__ gam, const float* __restrict__ bet,
                            float* __restrict__ X) {
    __shared__ float As[256 * 33];
    int j = blockIdx.x, i = threadIdx.x;
    float acc = b[j];
    for (int k0 = 0; k0 < K; k0 += 32) {
#pragma unroll
        for (int t = 0; t < 32; t++) {
            int idx = t * 256 + i;
            int r = idx >> 5, c = idx & 31;
            As[r * 33 + c] = A[r * K + k0 + c];
        }
        __syncthreads();
#pragma unroll
        for (int kk = 0; kk < 32; kk++)
            acc = fmaf(As[i * 33 + kk], W[(k0 + kk) * N + j], acc);
        __syncthreads();
    }
    __shared__ float red[256];
    red[i] = acc;
    __syncthreads();
    for (int off = 128; off > 0; off >>= 1) {
        if (i < off) red[i] += red[i + off];
        __syncthreads();
    }
    float mean = red[0] * (1.f / 256.f);
    __syncthreads();
    float d = acc - mean;
    red[i] = d * d;
    __syncthreads();
    for (int off = 128; off > 0; off >>= 1) {
        if (i < off) red[i] += red[i + off];
        __syncthreads();
    }
    float var = red[0] * (1.f / 256.f);
    X[i * N + j] = tanhf(d * rsqrtf(var + BN_EPS) * gam[j] + bet[j]);
}

// final linear (no BN); also re-zeroes g_pcnt for the next replay
__launch_bounds__(256)
__global__ void final_kernel(const float* __restrict__ A, const float* __restrict__ W,
                             const float* __restrict__ b, float* __restrict__ out) {
    __shared__ float As[256 * 33];
    int j = blockIdx.x, i = threadIdx.x;   // 10 blocks x 256 rows
    float acc = b[j];
    for (int k0 = 0; k0 < 64; k0 += 32) {
#pragma unroll
        for (int t = 0; t < 32; t++) {
            int idx = t * 256 + i;
            int r = idx >> 5, c = idx & 31;
            As[r * 33 + c] = A[r * 64 + k0 + c];
        }
        __syncthreads();
#pragma unroll
        for (int kk = 0; kk < 32; kk++)
            acc = fmaf(As[i * 33 + kk], W[(k0 + kk) * 10 + j], acc);
        __syncthreads();
    }
    out[i * 10 + j] = acc;
    if (j == 0) g_pcnt[i] = 0.f;
}

// ------------------------ launch --------------------------------------------
extern "C" void kernel_launch(void* const* d_in, const int* in_sizes, int n_in,
                              void* d_out, int out_size) {
    const float* x      = (const float*)d_in[0];
    const void*  ei     = d_in[1];
    const void*  bt     = d_in[2];
    const float* W1l    = (const float*)d_in[3];
    const float* b1l    = (const float*)d_in[4];
    const float* W1r    = (const float*)d_in[5];
    const float* W2l    = (const float*)d_in[6];
    const float* b2l    = (const float*)d_in[7];
    const float* W2r    = (const float*)d_in[8];
    const float* W3l    = (const float*)d_in[9];
    const float* b3l    = (const float*)d_in[10];
    const float* W3r    = (const float*)d_in[11];
    const float* lin1_w = (const float*)d_in[12];
    const float* lin1_b = (const float*)d_in[13];
    const float* g1     = (const float*)d_in[14];
    const float* be1    = (const float*)d_in[15];
    const float* lin2_w = (const float*)d_in[16];
    const float* lin2_b = (const float*)d_in[17];
    const float* g2     = (const float*)d_in[18];
    const float* be2    = (const float*)d_in[19];
    const float* lin3_w = (const float*)d_in[20];
    const float* lin3_b = (const float*)d_in[21];
    const float* g3     = (const float*)d_in[22];
    const float* be3    = (const float*)d_in[23];
    const float* lin4_w = (const float*)d_in[24];
    const float* lin4_b = (const float*)d_in[25];
    float* out = (float*)d_out;

    float *pY, *pZ, *pHA, *pHB, *pPool, *pT1, *pT2, *pT3;
    cudaGetSymbolAddress((void**)&pY,    g_y);
    cudaGetSymbolAddress((void**)&pZ,    g_z);
    cudaGetSymbolAddress((void**)&pHA,   g_hA);
    cudaGetSymbolAddress((void**)&pHB,   g_hB);
    cudaGetSymbolAddress((void**)&pPool, g_pool);
    cudaGetSymbolAddress((void**)&pT1,   g_t1);
    cudaGetSymbolAddress((void**)&pT2,   g_t2);
    cudaGetSymbolAddress((void**)&pT3,   g_t3);

    const int EB = (NE + 255) / 256;          // 3125
    const int MB = (NN + 127) / 128;          // 391
    const int WB = (NN * 32 + 255) / 256;     // 6250

    detect_kernel<<<1, 256>>>((const long long*)ei, (const long long*)bt);
    convert_kernel<<<EB, 256>>>(ei, bt);      // also builds degree histogram
    scan_kernel<<<1, 1024>>>();               // rowstart/cursor/invcnt + cnt reset
    fill_kernel<<<EB, 256>>>();

    // ---- layer 1 (K=128) ----
    gemm_fused<128><<<MB, 256>>>(x, W1l, W1r, b1l, pY, pZ);
    aggregate_kernel<false><<<WB, 256>>>(pHA);

    // ---- layer 2 (K=64) ----
    gemm_fused<64><<<MB, 256>>>(pHA, W2l, W2r, b2l, pY, pZ);
    aggregate_kernel<false><<<WB, 256>>>(pHB);

    // ---- layer 3 (K=64) + pooling fused ----
    gemm_fused<64><<<MB, 256>>>(pHB, W3l, W3r, b3l, pY, pZ);
    aggregate_kernel<true><<<WB, 256>>>(nullptr);

    poolnorm_kernel<<<(NG * H + 255) / 256, 256>>>();

    // ---- MLP head (fused gemm+BN+tanh per layer, smem-staged A) ----
    head_kernel<64, 256><<<256, 256>>>(pPool, lin1_w, lin1_b, g1, be1, pT1);
    head_kernel<256, 128><<<128, 256>>>(pT1, lin2_w, lin2_b, g2, be2, pT2);
    head_kernel<128, 64><<<64, 256>>>(pT2, lin3_w, lin3_b, g3, be3, pT3);
    final_kernel<<<10, 256>>>(pT3, lin4_w, lin4_b, out);
}